// round 2
// baseline (speedup 1.0000x reference)
#include <cuda_runtime.h>
#include <cuda_bf16.h>

#define NN 100000
#define EE 1600000
#define DD 64
#define KPROP 10

// ---------------- scratch (static device globals; no runtime allocation) ----
__device__ float g_deg[NN];
__device__ float g_dinv[NN];
__device__ float g_selfw[NN];
__device__ int   g_cnt[NN];
__device__ int   g_rowptr[NN + 1];
__device__ int   g_cols[EE];
__device__ float g_wn[EE];
__device__ float g_hA[NN * DD];
__device__ float g_hB[NN * DD];
__device__ float g_acc[NN * DD];
__device__ float g_z[NN * 256];

// ---------------- init: deg = 1 (self loop), cnt = 0 ------------------------
__global__ void init_kernel(int n) {
    int i = blockIdx.x * blockDim.x + threadIdx.x;
    if (i < n) { g_deg[i] = 1.0f; g_cnt[i] = 0; }
}

// ---------------- degree + row histogram ------------------------------------
__global__ void hist_kernel(const int* __restrict__ row,
                            const float* __restrict__ w, int e) {
    int i = blockIdx.x * blockDim.x + threadIdx.x;
    if (i < e) {
        int r = row[i];
        atomicAdd(&g_deg[r], w[i]);
        atomicAdd(&g_cnt[r], 1);
    }
}

// ---------------- dinv + self-loop weight -----------------------------------
__global__ void dinv_kernel(int n) {
    int i = blockIdx.x * blockDim.x + threadIdx.x;
    if (i < n) {
        float di = rsqrtf(fmaxf(g_deg[i], 1e-12f));
        g_dinv[i] = di;
        g_selfw[i] = di * di;
    }
}

// ---------------- single-block exclusive scan of g_cnt -> g_rowptr ----------
__global__ void scan_kernel(int n) {
    __shared__ int sums[1024];
    int t = threadIdx.x;
    int ch = (n + 1023) / 1024;
    int lo = t * ch;
    int hi = min(lo + ch, n);
    int s = 0;
    for (int i = lo; i < hi; ++i) s += g_cnt[i];
    sums[t] = s;
    __syncthreads();
    for (int off = 1; off < 1024; off <<= 1) {
        int v = (t >= off) ? sums[t - off] : 0;
        __syncthreads();
        sums[t] += v;
        __syncthreads();
    }
    int base = (t > 0) ? sums[t - 1] : 0;
    for (int i = lo; i < hi; ++i) {
        int c = g_cnt[i];
        g_rowptr[i] = base;
        base += c;
        g_cnt[i] = 0;   // reset: reused as scatter cursors
    }
    if (t == 1023) g_rowptr[n] = sums[1023];
}

// ---------------- scatter edges into CSR with normalized weights ------------
__global__ void scatter_kernel(const int* __restrict__ row,
                               const int* __restrict__ col,
                               const float* __restrict__ w, int e) {
    int i = blockIdx.x * blockDim.x + threadIdx.x;
    if (i < e) {
        int r = row[i];
        int c = col[i];
        int pos = g_rowptr[r] + atomicAdd(&g_cnt[r], 1);
        g_cols[pos] = c;
        g_wn[pos] = g_dinv[r] * w[i] * g_dinv[c];
    }
}

// ---------------- SpMM step: warp per row, float2 per lane ------------------
__global__ void spmm_kernel(const float* __restrict__ x, int iter, int n) {
    int gw = (blockIdx.x * blockDim.x + threadIdx.x) >> 5;
    if (gw >= n) return;
    int lane = threadIdx.x & 31;

    const float* hin = (iter == 0) ? x : ((iter & 1) ? g_hA : g_hB);
    float* hout = (iter & 1) ? g_hB : g_hA;
    const float2* __restrict__ hin2 = (const float2*)hin;

    int i = gw;
    float sw = g_selfw[i];
    float2 hv = hin2[i * 32 + lane];
    float ax = sw * hv.x;
    float ay = sw * hv.y;

    int s = g_rowptr[i];
    int e = g_rowptr[i + 1];
    for (int p = s; p < e; ++p) {
        int c = g_cols[p];
        float wv = g_wn[p];
        float2 src = hin2[c * 32 + lane];
        ax += wv * src.x;
        ay += wv * src.y;
    }

    float2 r; r.x = ax; r.y = ay;
    ((float2*)hout)[i * 32 + lane] = r;

    float2* accp = (float2*)g_acc;
    if (iter == 0) {
        accp[i * 32 + lane] = r;
    } else {
        float2 t = accp[i * 32 + lane];
        t.x += ax; t.y += ay;
        accp[i * 32 + lane] = t;
    }
}

// ---------------- GEMM1: z = relu((0.1x + 0.09acc) @ W0 + b0)   [M,64]x[64,256]
__global__ void gemm1_kernel(const float* __restrict__ x,
                             const float* __restrict__ W0,
                             const float* __restrict__ b0, int M) {
    __shared__ float As[16][68];
    __shared__ float Bs[16][68];
    int m0 = blockIdx.x * 64;
    int n0 = blockIdx.y * 64;
    int tid = threadIdx.x;
    int ty = tid >> 4, tx = tid & 15;

    float acc[4][4];
#pragma unroll
    for (int i = 0; i < 4; ++i)
#pragma unroll
        for (int j = 0; j < 4; ++j) acc[i][j] = 0.0f;

    int am = tid >> 2;
    int ak = (tid & 3) * 4;
    int kb = tid >> 4;
    int bn = (tid & 15) * 4;

    for (int k0 = 0; k0 < 64; k0 += 16) {
        int gm = m0 + am;
        float4 av = make_float4(0.f, 0.f, 0.f, 0.f);
        if (gm < M) {
            float4 xv = *(const float4*)(x + (size_t)gm * 64 + k0 + ak);
            float4 cv = *(const float4*)(g_acc + (size_t)gm * 64 + k0 + ak);
            av.x = 0.1f * xv.x + 0.09f * cv.x;
            av.y = 0.1f * xv.y + 0.09f * cv.y;
            av.z = 0.1f * xv.z + 0.09f * cv.z;
            av.w = 0.1f * xv.w + 0.09f * cv.w;
        }
        As[ak + 0][am] = av.x;
        As[ak + 1][am] = av.y;
        As[ak + 2][am] = av.z;
        As[ak + 3][am] = av.w;
        *(float4*)&Bs[kb][bn] =
            *(const float4*)(W0 + (size_t)(k0 + kb) * 256 + n0 + bn);
        __syncthreads();
#pragma unroll
        for (int k = 0; k < 16; ++k) {
            float4 a4 = *(float4*)&As[k][4 * ty];
            float4 b4 = *(float4*)&Bs[k][4 * tx];
            acc[0][0] += a4.x * b4.x; acc[0][1] += a4.x * b4.y;
            acc[0][2] += a4.x * b4.z; acc[0][3] += a4.x * b4.w;
            acc[1][0] += a4.y * b4.x; acc[1][1] += a4.y * b4.y;
            acc[1][2] += a4.y * b4.z; acc[1][3] += a4.y * b4.w;
            acc[2][0] += a4.z * b4.x; acc[2][1] += a4.z * b4.y;
            acc[2][2] += a4.z * b4.z; acc[2][3] += a4.z * b4.w;
            acc[3][0] += a4.w * b4.x; acc[3][1] += a4.w * b4.y;
            acc[3][2] += a4.w * b4.z; acc[3][3] += a4.w * b4.w;
        }
        __syncthreads();
    }

    float4 bias = *(const float4*)(b0 + n0 + 4 * tx);
#pragma unroll
    for (int j = 0; j < 4; ++j) {
        int gm = m0 + 4 * ty + j;
        if (gm < M) {
            float4 o;
            o.x = fmaxf(acc[j][0] + bias.x, 0.0f);
            o.y = fmaxf(acc[j][1] + bias.y, 0.0f);
            o.z = fmaxf(acc[j][2] + bias.z, 0.0f);
            o.w = fmaxf(acc[j][3] + bias.w, 0.0f);
            *(float4*)(g_z + (size_t)gm * 256 + n0 + 4 * tx) = o;
        }
    }
}

// ---------------- GEMM2: out = z @ W1 + b1   [M,256]x[256,64] ----------------
__global__ void gemm2_kernel(const float* __restrict__ W1,
                             const float* __restrict__ b1,
                             float* __restrict__ out, int M) {
    __shared__ float As[16][68];
    __shared__ float Bs[16][68];
    int m0 = blockIdx.x * 64;
    int tid = threadIdx.x;
    int ty = tid >> 4, tx = tid & 15;

    float acc[4][4];
#pragma unroll
    for (int i = 0; i < 4; ++i)
#pragma unroll
        for (int j = 0; j < 4; ++j) acc[i][j] = 0.0f;

    int am = tid >> 2;
    int ak = (tid & 3) * 4;
    int kb = tid >> 4;
    int bn = (tid & 15) * 4;

    for (int k0 = 0; k0 < 256; k0 += 16) {
        int gm = m0 + am;
        float4 av = make_float4(0.f, 0.f, 0.f, 0.f);
        if (gm < M) av = *(const float4*)(g_z + (size_t)gm * 256 + k0 + ak);
        As[ak + 0][am] = av.x;
        As[ak + 1][am] = av.y;
        As[ak + 2][am] = av.z;
        As[ak + 3][am] = av.w;
        *(float4*)&Bs[kb][bn] =
            *(const float4*)(W1 + (size_t)(k0 + kb) * 64 + bn);
        __syncthreads();
#pragma unroll
        for (int k = 0; k < 16; ++k) {
            float4 a4 = *(float4*)&As[k][4 * ty];
            float4 b4 = *(float4*)&Bs[k][4 * tx];
            acc[0][0] += a4.x * b4.x; acc[0][1] += a4.x * b4.y;
            acc[0][2] += a4.x * b4.z; acc[0][3] += a4.x * b4.w;
            acc[1][0] += a4.y * b4.x; acc[1][1] += a4.y * b4.y;
            acc[1][2] += a4.y * b4.z; acc[1][3] += a4.y * b4.w;
            acc[2][0] += a4.z * b4.x; acc[2][1] += a4.z * b4.y;
            acc[2][2] += a4.z * b4.z; acc[2][3] += a4.z * b4.w;
            acc[3][0] += a4.w * b4.x; acc[3][1] += a4.w * b4.y;
            acc[3][2] += a4.w * b4.z; acc[3][3] += a4.w * b4.w;
        }
        __syncthreads();
    }

    float4 bias = *(const float4*)(b1 + 4 * tx);
#pragma unroll
    for (int j = 0; j < 4; ++j) {
        int gm = m0 + 4 * ty + j;
        if (gm < M) {
            float4 o;
            o.x = acc[j][0] + bias.x;
            o.y = acc[j][1] + bias.y;
            o.z = acc[j][2] + bias.z;
            o.w = acc[j][3] + bias.w;
            *(float4*)(out + (size_t)gm * 64 + 4 * tx) = o;
        }
    }
}

// ---------------- launcher ---------------------------------------------------
extern "C" void kernel_launch(void* const* d_in, const int* in_sizes, int n_in,
                              void* d_out, int out_size) {
    const float* x  = (const float*)d_in[0];
    const int*   ei = (const int*)d_in[1];
    const float* ew = (const float*)d_in[2];
    const float* W0 = (const float*)d_in[3];
    const float* b0 = (const float*)d_in[4];
    const float* W1 = (const float*)d_in[5];
    const float* b1 = (const float*)d_in[6];
    float* out = (float*)d_out;

    int n = in_sizes[0] / DD;
    int e = in_sizes[2];
    const int* row = ei;
    const int* col = ei + e;

    init_kernel<<<(n + 255) / 256, 256>>>(n);
    hist_kernel<<<(e + 255) / 256, 256>>>(row, ew, e);
    dinv_kernel<<<(n + 255) / 256, 256>>>(n);
    scan_kernel<<<1, 1024>>>(n);
    scatter_kernel<<<(e + 255) / 256, 256>>>(row, col, ew, e);

    int spmm_grid = (n + 7) / 8;   // 8 warps (rows) per 256-thread block
    for (int it = 0; it < KPROP; ++it)
        spmm_kernel<<<spmm_grid, 256>>>(x, it, n);

    int mblocks = (n + 63) / 64;
    gemm1_kernel<<<dim3(mblocks, 4), 256>>>(x, W0, b0, n);
    gemm2_kernel<<<dim3(mblocks, 1), 256>>>(W1, b1, out, n);
}

// round 5
// speedup vs baseline: 1.0331x; 1.0331x over previous
#include <cuda_runtime.h>
#include <cuda_fp16.h>
#include <cuda_bf16.h>

#define NN 100000
#define EE 1600000
#define DD 64
#define KPROP 10

// ---------------- scratch (static device globals; no runtime allocation) ----
__device__ float  g_deg[NN];
__device__ float  g_dinv[NN];
__device__ float  g_selfw[NN];
__device__ int    g_cnt[NN];
__device__ int    g_rowptr[NN + 1];
__device__ int    g_cols[EE];
__device__ float  g_wn[EE];
__device__ __half g_x16[NN * DD];   // fp16 copy of x
__device__ __half g_h16A[NN * DD];  // ping
__device__ __half g_h16B[NN * DD];  // pong
__device__ float  g_acc[NN * DD];   // fp32 accumulator of sum_l A^l x
__device__ float  g_z[NN * 256];

// ---------------- init: deg = 1 (self loop), cnt = 0 ------------------------
__global__ void init_kernel(int n) {
    int i = blockIdx.x * blockDim.x + threadIdx.x;
    if (i < n) { g_deg[i] = 1.0f; g_cnt[i] = 0; }
}

// ---------------- degree + row histogram ------------------------------------
__global__ void hist_kernel(const int* __restrict__ row,
                            const float* __restrict__ w, int e) {
    int i = blockIdx.x * blockDim.x + threadIdx.x;
    if (i < e) {
        int r = row[i];
        atomicAdd(&g_deg[r], w[i]);
        atomicAdd(&g_cnt[r], 1);
    }
}

// ---------------- dinv + self-loop weight -----------------------------------
__global__ void dinv_kernel(int n) {
    int i = blockIdx.x * blockDim.x + threadIdx.x;
    if (i < n) {
        float di = rsqrtf(fmaxf(g_deg[i], 1e-12f));
        g_dinv[i] = di;
        g_selfw[i] = di * di;
    }
}

// ---------------- x (fp32) -> g_x16 (fp16), half2-packed --------------------
__global__ void tofp16_kernel(const float* __restrict__ x, int n2) {
    int i = blockIdx.x * blockDim.x + threadIdx.x;
    if (i < n2) {
        float2 f = ((const float2*)x)[i];
        ((__half2*)g_x16)[i] = __floats2half2_rn(f.x, f.y);
    }
}

// ---------------- single-block exclusive scan of g_cnt -> g_rowptr ----------
__global__ void scan_kernel(int n) {
    __shared__ int sums[1024];
    int t = threadIdx.x;
    int ch = (n + 1023) / 1024;
    int lo = t * ch;
    int hi = min(lo + ch, n);
    int s = 0;
    for (int i = lo; i < hi; ++i) s += g_cnt[i];
    sums[t] = s;
    __syncthreads();
    for (int off = 1; off < 1024; off <<= 1) {
        int v = (t >= off) ? sums[t - off] : 0;
        __syncthreads();
        sums[t] += v;
        __syncthreads();
    }
    int base = (t > 0) ? sums[t - 1] : 0;
    for (int i = lo; i < hi; ++i) {
        int c = g_cnt[i];
        g_rowptr[i] = base;
        base += c;
        g_cnt[i] = 0;   // reset: reused as scatter cursors
    }
    if (t == 1023) g_rowptr[n] = sums[1023];
}

// ---------------- scatter edges into CSR with normalized weights ------------
__global__ void scatter_kernel(const int* __restrict__ row,
                               const int* __restrict__ col,
                               const float* __restrict__ w, int e) {
    int i = blockIdx.x * blockDim.x + threadIdx.x;
    if (i < e) {
        int r = row[i];
        int c = col[i];
        int pos = g_rowptr[r] + atomicAdd(&g_cnt[r], 1);
        g_cols[pos] = c;
        g_wn[pos] = g_dinv[r] * w[i] * g_dinv[c];
    }
}

// ---------------- SpMM step: warp per row, fp16 rows (half2/lane) -----------
// Buffers selected DEVICE-SIDE from iter (host may not take __device__ symbol
// addresses). Edges consumed in chunks of 32: one coalesced load of (col, w),
// then shfl-broadcast: per edge = 1 gather LDG + 2 SHFL + 2 FMA.
__global__ void spmm_kernel(int iter, int n) {
    int gw = (blockIdx.x * blockDim.x + threadIdx.x) >> 5;
    if (gw >= n) return;
    int lane = threadIdx.x & 31;

    const __half2* __restrict__ hin =
        (iter == 0) ? (const __half2*)g_x16
                    : ((iter & 1) ? (const __half2*)g_h16A
                                  : (const __half2*)g_h16B);
    __half2* __restrict__ hout =
        (iter & 1) ? (__half2*)g_h16B : (__half2*)g_h16A;

    float sw = g_selfw[gw];
    float2 hv = __half22float2(hin[gw * 32 + lane]);
    float ax = sw * hv.x;
    float ay = sw * hv.y;

    int s = g_rowptr[gw];
    int e = g_rowptr[gw + 1];
    for (int base = s; base < e; base += 32) {
        int cnt = min(32, e - base);
        int c = 0;
        float wv = 0.0f;
        if (lane < cnt) {
            c  = g_cols[base + lane];
            wv = g_wn[base + lane];
        }
#pragma unroll 4
        for (int j = 0; j < cnt; ++j) {
            int   cc = __shfl_sync(0xffffffffu, c, j);
            float ww = __shfl_sync(0xffffffffu, wv, j);
            float2 f = __half22float2(hin[cc * 32 + lane]);
            ax += ww * f.x;
            ay += ww * f.y;
        }
    }

    hout[gw * 32 + lane] = __floats2half2_rn(ax, ay);

    float2* accp = (float2*)g_acc;
    if (iter == 0) {
        accp[gw * 32 + lane] = make_float2(ax, ay);
    } else {
        float2 t = accp[gw * 32 + lane];
        t.x += ax; t.y += ay;
        accp[gw * 32 + lane] = t;
    }
}

// ---------------- GEMM1: z = relu((0.1x + 0.09acc) @ W0 + b0)   [M,64]x[64,256]
__global__ void gemm1_kernel(const float* __restrict__ x,
                             const float* __restrict__ W0,
                             const float* __restrict__ b0, int M) {
    __shared__ float As[16][68];
    __shared__ float Bs[16][68];
    int m0 = blockIdx.x * 64;
    int n0 = blockIdx.y * 64;
    int tid = threadIdx.x;
    int ty = tid >> 4, tx = tid & 15;

    float acc[4][4];
#pragma unroll
    for (int i = 0; i < 4; ++i)
#pragma unroll
        for (int j = 0; j < 4; ++j) acc[i][j] = 0.0f;

    int am = tid >> 2;
    int ak = (tid & 3) * 4;
    int kb = tid >> 4;
    int bn = (tid & 15) * 4;

    for (int k0 = 0; k0 < 64; k0 += 16) {
        int gm = m0 + am;
        float4 av = make_float4(0.f, 0.f, 0.f, 0.f);
        if (gm < M) {
            float4 xv = *(const float4*)(x + (size_t)gm * 64 + k0 + ak);
            float4 cv = *(const float4*)(g_acc + (size_t)gm * 64 + k0 + ak);
            av.x = 0.1f * xv.x + 0.09f * cv.x;
            av.y = 0.1f * xv.y + 0.09f * cv.y;
            av.z = 0.1f * xv.z + 0.09f * cv.z;
            av.w = 0.1f * xv.w + 0.09f * cv.w;
        }
        As[ak + 0][am] = av.x;
        As[ak + 1][am] = av.y;
        As[ak + 2][am] = av.z;
        As[ak + 3][am] = av.w;
        *(float4*)&Bs[kb][bn] =
            *(const float4*)(W0 + (size_t)(k0 + kb) * 256 + n0 + bn);
        __syncthreads();
#pragma unroll
        for (int k = 0; k < 16; ++k) {
            float4 a4 = *(float4*)&As[k][4 * ty];
            float4 b4 = *(float4*)&Bs[k][4 * tx];
            acc[0][0] += a4.x * b4.x; acc[0][1] += a4.x * b4.y;
            acc[0][2] += a4.x * b4.z; acc[0][3] += a4.x * b4.w;
            acc[1][0] += a4.y * b4.x; acc[1][1] += a4.y * b4.y;
            acc[1][2] += a4.y * b4.z; acc[1][3] += a4.y * b4.w;
            acc[2][0] += a4.z * b4.x; acc[2][1] += a4.z * b4.y;
            acc[2][2] += a4.z * b4.z; acc[2][3] += a4.z * b4.w;
            acc[3][0] += a4.w * b4.x; acc[3][1] += a4.w * b4.y;
            acc[3][2] += a4.w * b4.z; acc[3][3] += a4.w * b4.w;
        }
        __syncthreads();
    }

    float4 bias = *(const float4*)(b0 + n0 + 4 * tx);
#pragma unroll
    for (int j = 0; j < 4; ++j) {
        int gm = m0 + 4 * ty + j;
        if (gm < M) {
            float4 o;
            o.x = fmaxf(acc[j][0] + bias.x, 0.0f);
            o.y = fmaxf(acc[j][1] + bias.y, 0.0f);
            o.z = fmaxf(acc[j][2] + bias.z, 0.0f);
            o.w = fmaxf(acc[j][3] + bias.w, 0.0f);
            *(float4*)(g_z + (size_t)gm * 256 + n0 + 4 * tx) = o;
        }
    }
}

// ---------------- GEMM2: out = z @ W1 + b1   [M,256]x[256,64] ----------------
__global__ void gemm2_kernel(const float* __restrict__ W1,
                             const float* __restrict__ b1,
                             float* __restrict__ out, int M) {
    __shared__ float As[16][68];
    __shared__ float Bs[16][68];
    int m0 = blockIdx.x * 64;
    int tid = threadIdx.x;
    int ty = tid >> 4, tx = tid & 15;

    float acc[4][4];
#pragma unroll
    for (int i = 0; i < 4; ++i)
#pragma unroll
        for (int j = 0; j < 4; ++j) acc[i][j] = 0.0f;

    int am = tid >> 2;
    int ak = (tid & 3) * 4;
    int kb = tid >> 4;
    int bn = (tid & 15) * 4;

    for (int k0 = 0; k0 < 256; k0 += 16) {
        int gm = m0 + am;
        float4 av = make_float4(0.f, 0.f, 0.f, 0.f);
        if (gm < M) av = *(const float4*)(g_z + (size_t)gm * 256 + k0 + ak);
        As[ak + 0][am] = av.x;
        As[ak + 1][am] = av.y;
        As[ak + 2][am] = av.z;
        As[ak + 3][am] = av.w;
        *(float4*)&Bs[kb][bn] =
            *(const float4*)(W1 + (size_t)(k0 + kb) * 64 + bn);
        __syncthreads();
#pragma unroll
        for (int k = 0; k < 16; ++k) {
            float4 a4 = *(float4*)&As[k][4 * ty];
            float4 b4 = *(float4*)&Bs[k][4 * tx];
            acc[0][0] += a4.x * b4.x; acc[0][1] += a4.x * b4.y;
            acc[0][2] += a4.x * b4.z; acc[0][3] += a4.x * b4.w;
            acc[1][0] += a4.y * b4.x; acc[1][1] += a4.y * b4.y;
            acc[1][2] += a4.y * b4.z; acc[1][3] += a4.y * b4.w;
            acc[2][0] += a4.z * b4.x; acc[2][1] += a4.z * b4.y;
            acc[2][2] += a4.z * b4.z; acc[2][3] += a4.z * b4.w;
            acc[3][0] += a4.w * b4.x; acc[3][1] += a4.w * b4.y;
            acc[3][2] += a4.w * b4.z; acc[3][3] += a4.w * b4.w;
        }
        __syncthreads();
    }

    float4 bias = *(const float4*)(b1 + 4 * tx);
#pragma unroll
    for (int j = 0; j < 4; ++j) {
        int gm = m0 + 4 * ty + j;
        if (gm < M) {
            float4 o;
            o.x = acc[j][0] + bias.x;
            o.y = acc[j][1] + bias.y;
            o.z = acc[j][2] + bias.z;
            o.w = acc[j][3] + bias.w;
            *(float4*)(out + (size_t)gm * 64 + 4 * tx) = o;
        }
    }
}

// ---------------- launcher ---------------------------------------------------
extern "C" void kernel_launch(void* const* d_in, const int* in_sizes, int n_in,
                              void* d_out, int out_size) {
    const float* x  = (const float*)d_in[0];
    const int*   ei = (const int*)d_in[1];
    const float* ew = (const float*)d_in[2];
    const float* W0 = (const float*)d_in[3];
    const float* b0 = (const float*)d_in[4];
    const float* W1 = (const float*)d_in[5];
    const float* b1 = (const float*)d_in[6];
    float* out = (float*)d_out;

    int n = in_sizes[0] / DD;
    int e = in_sizes[2];
    const int* row = ei;
    const int* col = ei + e;

    init_kernel<<<(n + 255) / 256, 256>>>(n);
    hist_kernel<<<(e + 255) / 256, 256>>>(row, ew, e);
    dinv_kernel<<<(n + 255) / 256, 256>>>(n);
    tofp16_kernel<<<(n * DD / 2 + 255) / 256, 256>>>(x, n * DD / 2);
    scan_kernel<<<1, 1024>>>(n);
    scatter_kernel<<<(e + 255) / 256, 256>>>(row, col, ew, e);

    int spmm_grid = (n + 7) / 8;   // 8 warps (rows) per 256-thread block
    for (int it = 0; it < KPROP; ++it)
        spmm_kernel<<<spmm_grid, 256>>>(it, n);

    int mblocks = (n + 63) / 64;
    gemm1_kernel<<<dim3(mblocks, 4), 256>>>(x, W0, b0, n);
    gemm2_kernel<<<dim3(mblocks, 1), 256>>>(W1, b1, out, n);
}

// round 7
// speedup vs baseline: 1.1289x; 1.0928x over previous
#include <cuda_runtime.h>
#include <cuda_fp16.h>
#include <cuda_bf16.h>

#define NN 100000
#define EE 1600000
#define DD 64
#define KPROP 10

// ---------------- scratch (static device globals; no runtime allocation) ----
__device__ float  g_deg[NN];
__device__ float  g_dinv[NN];
__device__ float  g_selfw[NN];
__device__ int    g_cnt[NN];
__device__ int    g_rowptr[NN + 1];
__device__ int    g_cols[EE];
__device__ float  g_wn[EE];
__device__ __align__(16) __half g_x16[NN * DD];   // fp16 copy of x
__device__ __align__(16) __half g_h16A[NN * DD];  // ping
__device__ __align__(16) __half g_h16B[NN * DD];  // pong
__device__ __align__(16) float  g_acc[NN * DD];   // fp32 acc of sum_l A^l x
__device__ __align__(16) float  g_z[NN * 256];

// ---------------- fused: deg=1, cnt=0, x->fp16 -------------------------------
__global__ void init_cvt_kernel(const float* __restrict__ x, int n, int n2) {
    int i = blockIdx.x * blockDim.x + threadIdx.x;
    if (i < n) { g_deg[i] = 1.0f; g_cnt[i] = 0; }
    if (i < n2) {
        float2 f = ((const float2*)x)[i];
        ((__half2*)g_x16)[i] = __floats2half2_rn(f.x, f.y);
    }
}

// ---------------- degree + row histogram ------------------------------------
__global__ void hist_kernel(const int* __restrict__ row,
                            const float* __restrict__ w, int e) {
    int i = blockIdx.x * blockDim.x + threadIdx.x;
    if (i < e) {
        int r = row[i];
        atomicAdd(&g_deg[r], w[i]);
        atomicAdd(&g_cnt[r], 1);
    }
}

// ---------------- dinv + self-loop weight -----------------------------------
__global__ void dinv_kernel(int n) {
    int i = blockIdx.x * blockDim.x + threadIdx.x;
    if (i < n) {
        float di = rsqrtf(fmaxf(g_deg[i], 1e-12f));
        g_dinv[i] = di;
        g_selfw[i] = di * di;
    }
}

// ---------------- single-block exclusive scan of g_cnt -> g_rowptr ----------
__global__ void scan_kernel(int n) {
    __shared__ int sums[1024];
    int t = threadIdx.x;
    int ch = (n + 1023) / 1024;
    int lo = t * ch;
    int hi = min(lo + ch, n);
    int s = 0;
    for (int i = lo; i < hi; ++i) s += g_cnt[i];
    sums[t] = s;
    __syncthreads();
    for (int off = 1; off < 1024; off <<= 1) {
        int v = (t >= off) ? sums[t - off] : 0;
        __syncthreads();
        sums[t] += v;
        __syncthreads();
    }
    int base = (t > 0) ? sums[t - 1] : 0;
    for (int i = lo; i < hi; ++i) {
        int c = g_cnt[i];
        g_rowptr[i] = base;
        base += c;
        g_cnt[i] = 0;   // reset: reused as scatter cursors
    }
    if (t == 1023) g_rowptr[n] = sums[1023];
}

// ---------------- scatter edges into CSR with normalized weights ------------
__global__ void scatter_kernel(const int* __restrict__ row,
                               const int* __restrict__ col,
                               const float* __restrict__ w, int e) {
    int i = blockIdx.x * blockDim.x + threadIdx.x;
    if (i < e) {
        int r = row[i];
        int c = col[i];
        int pos = g_rowptr[r] + atomicAdd(&g_cnt[r], 1);
        g_cols[pos] = c;
        g_wn[pos] = g_dinv[r] * w[i] * g_dinv[c];
    }
}

// ---------------- SpMM step: warp per row, 8 lanes/edge, 4 edges/pass -------
// Each pass: one warp-wide LDG.128 pulls 4 full 128B fp16 source rows.
// Edge metadata via 8-lane broadcast LDG (no shfl -> no address dependency).
// fp32 accumulators; butterfly reduce over the 4 edge groups at row end.
__global__ void spmm_kernel(int iter, int n) {
    int gw = (blockIdx.x * blockDim.x + threadIdx.x) >> 5;
    if (gw >= n) return;
    int lane = threadIdx.x & 31;
    int g   = lane >> 3;   // edge group 0..3
    int sub = lane & 7;    // 16B chunk within 128B row

    const uint4* __restrict__ hin4 =
        (iter == 0) ? (const uint4*)g_x16
                    : ((iter & 1) ? (const uint4*)g_h16A
                                  : (const uint4*)g_h16B);
    uint4* __restrict__ hout4 =
        (iter & 1) ? (uint4*)g_h16B : (uint4*)g_h16A;

    float acc[8];
#pragma unroll
    for (int k = 0; k < 8; ++k) acc[k] = 0.0f;

    int s = g_rowptr[gw];
    int e = g_rowptr[gw + 1];
    int d = e - s;
    int full = d >> 2;
    int epb = s + g;

#pragma unroll 2
    for (int j = 0; j < full; ++j) {
        int ep = epb + j * 4;
        int   cc = __ldg(&g_cols[ep]);
        float ww = __ldg(&g_wn[ep]);
        uint4 v = hin4[(size_t)cc * 8 + sub];
        const __half2* hp = (const __half2*)&v;
#pragma unroll
        for (int q = 0; q < 4; ++q) {
            float2 f = __half22float2(hp[q]);
            acc[2 * q]     = fmaf(ww, f.x, acc[2 * q]);
            acc[2 * q + 1] = fmaf(ww, f.y, acc[2 * q + 1]);
        }
    }
    int r = d & 3;
    if (r) {
        int ep = epb + full * 4;
        int cc = 0;
        float ww = 0.0f;
        if (g < r) { cc = g_cols[ep]; ww = g_wn[ep]; }
        uint4 v = hin4[(size_t)cc * 8 + sub];
        const __half2* hp = (const __half2*)&v;
#pragma unroll
        for (int q = 0; q < 4; ++q) {
            float2 f = __half22float2(hp[q]);
            acc[2 * q]     = fmaf(ww, f.x, acc[2 * q]);
            acc[2 * q + 1] = fmaf(ww, f.y, acc[2 * q + 1]);
        }
    }

    // reduce the 4 edge groups (lanes differ in bits 3,4)
#pragma unroll
    for (int off = 8; off <= 16; off <<= 1)
#pragma unroll
        for (int k = 0; k < 8; ++k)
            acc[k] += __shfl_xor_sync(0xffffffffu, acc[k], off);

    if (lane < 8) {
        // self-loop contribution
        float sw = g_selfw[gw];
        uint4 own = hin4[(size_t)gw * 8 + sub];
        const __half2* op = (const __half2*)&own;
#pragma unroll
        for (int q = 0; q < 4; ++q) {
            float2 f = __half22float2(op[q]);
            acc[2 * q]     = fmaf(sw, f.x, acc[2 * q]);
            acc[2 * q + 1] = fmaf(sw, f.y, acc[2 * q + 1]);
        }
        // write fp16 row
        uint4 outv;
        __half2* ov = (__half2*)&outv;
#pragma unroll
        for (int q = 0; q < 4; ++q)
            ov[q] = __floats2half2_rn(acc[2 * q], acc[2 * q + 1]);
        hout4[(size_t)gw * 8 + sub] = outv;

        // fp32 acc RMW (row = 16 float4; this lane owns 2 of them)
        float4* accp = (float4*)g_acc;
        size_t ai = (size_t)gw * 16 + sub * 2;
        if (iter == 0) {
            accp[ai]     = make_float4(acc[0], acc[1], acc[2], acc[3]);
            accp[ai + 1] = make_float4(acc[4], acc[5], acc[6], acc[7]);
        } else {
            float4 t0 = accp[ai], t1 = accp[ai + 1];
            t0.x += acc[0]; t0.y += acc[1]; t0.z += acc[2]; t0.w += acc[3];
            t1.x += acc[4]; t1.y += acc[5]; t1.z += acc[6]; t1.w += acc[7];
            accp[ai] = t0; accp[ai + 1] = t1;
        }
    }
}

// ---------------- GEMM1: z = relu((0.1x + 0.09acc) @ W0 + b0)   [M,64]x[64,256]
__global__ void gemm1_kernel(const float* __restrict__ x,
                             const float* __restrict__ W0,
                             const float* __restrict__ b0, int M) {
    __shared__ float As[16][68];
    __shared__ float Bs[16][68];
    int m0 = blockIdx.x * 64;
    int n0 = blockIdx.y * 64;
    int tid = threadIdx.x;
    int ty = tid >> 4, tx = tid & 15;

    float acc[4][4];
#pragma unroll
    for (int i = 0; i < 4; ++i)
#pragma unroll
        for (int j = 0; j < 4; ++j) acc[i][j] = 0.0f;

    int am = tid >> 2;
    int ak = (tid & 3) * 4;
    int kb = tid >> 4;
    int bn = (tid & 15) * 4;

    for (int k0 = 0; k0 < 64; k0 += 16) {
        int gm = m0 + am;
        float4 av = make_float4(0.f, 0.f, 0.f, 0.f);
        if (gm < M) {
            float4 xv = *(const float4*)(x + (size_t)gm * 64 + k0 + ak);
            float4 cv = *(const float4*)(g_acc + (size_t)gm * 64 + k0 + ak);
            av.x = 0.1f * xv.x + 0.09f * cv.x;
            av.y = 0.1f * xv.y + 0.09f * cv.y;
            av.z = 0.1f * xv.z + 0.09f * cv.z;
            av.w = 0.1f * xv.w + 0.09f * cv.w;
        }
        As[ak + 0][am] = av.x;
        As[ak + 1][am] = av.y;
        As[ak + 2][am] = av.z;
        As[ak + 3][am] = av.w;
        *(float4*)&Bs[kb][bn] =
            *(const float4*)(W0 + (size_t)(k0 + kb) * 256 + n0 + bn);
        __syncthreads();
#pragma unroll
        for (int k = 0; k < 16; ++k) {
            float4 a4 = *(float4*)&As[k][4 * ty];
            float4 b4 = *(float4*)&Bs[k][4 * tx];
            acc[0][0] += a4.x * b4.x; acc[0][1] += a4.x * b4.y;
            acc[0][2] += a4.x * b4.z; acc[0][3] += a4.x * b4.w;
            acc[1][0] += a4.y * b4.x; acc[1][1] += a4.y * b4.y;
            acc[1][2] += a4.y * b4.z; acc[1][3] += a4.y * b4.w;
            acc[2][0] += a4.z * b4.x; acc[2][1] += a4.z * b4.y;
            acc[2][2] += a4.z * b4.z; acc[2][3] += a4.z * b4.w;
            acc[3][0] += a4.w * b4.x; acc[3][1] += a4.w * b4.y;
            acc[3][2] += a4.w * b4.z; acc[3][3] += a4.w * b4.w;
        }
        __syncthreads();
    }

    float4 bias = *(const float4*)(b0 + n0 + 4 * tx);
#pragma unroll
    for (int j = 0; j < 4; ++j) {
        int gm = m0 + 4 * ty + j;
        if (gm < M) {
            float4 o;
            o.x = fmaxf(acc[j][0] + bias.x, 0.0f);
            o.y = fmaxf(acc[j][1] + bias.y, 0.0f);
            o.z = fmaxf(acc[j][2] + bias.z, 0.0f);
            o.w = fmaxf(acc[j][3] + bias.w, 0.0f);
            *(float4*)(g_z + (size_t)gm * 256 + n0 + 4 * tx) = o;
        }
    }
}

// ---------------- GEMM2: out = z @ W1 + b1   [M,256]x[256,64] ----------------
__global__ void gemm2_kernel(const float* __restrict__ W1,
                             const float* __restrict__ b1,
                             float* __restrict__ out, int M) {
    __shared__ float As[16][68];
    __shared__ float Bs[16][68];
    int m0 = blockIdx.x * 64;
    int tid = threadIdx.x;
    int ty = tid >> 4, tx = tid & 15;

    float acc[4][4];
#pragma unroll
    for (int i = 0; i < 4; ++i)
#pragma unroll
        for (int j = 0; j < 4; ++j) acc[i][j] = 0.0f;

    int am = tid >> 2;
    int ak = (tid & 3) * 4;
    int kb = tid >> 4;
    int bn = (tid & 15) * 4;

    for (int k0 = 0; k0 < 256; k0 += 16) {
        int gm = m0 + am;
        float4 av = make_float4(0.f, 0.f, 0.f, 0.f);
        if (gm < M) av = *(const float4*)(g_z + (size_t)gm * 256 + k0 + ak);
        As[ak + 0][am] = av.x;
        As[ak + 1][am] = av.y;
        As[ak + 2][am] = av.z;
        As[ak + 3][am] = av.w;
        *(float4*)&Bs[kb][bn] =
            *(const float4*)(W1 + (size_t)(k0 + kb) * 64 + bn);
        __syncthreads();
#pragma unroll
        for (int k = 0; k < 16; ++k) {
            float4 a4 = *(float4*)&As[k][4 * ty];
            float4 b4 = *(float4*)&Bs[k][4 * tx];
            acc[0][0] += a4.x * b4.x; acc[0][1] += a4.x * b4.y;
            acc[0][2] += a4.x * b4.z; acc[0][3] += a4.x * b4.w;
            acc[1][0] += a4.y * b4.x; acc[1][1] += a4.y * b4.y;
            acc[1][2] += a4.y * b4.z; acc[1][3] += a4.y * b4.w;
            acc[2][0] += a4.z * b4.x; acc[2][1] += a4.z * b4.y;
            acc[2][2] += a4.z * b4.z; acc[2][3] += a4.z * b4.w;
            acc[3][0] += a4.w * b4.x; acc[3][1] += a4.w * b4.y;
            acc[3][2] += a4.w * b4.z; acc[3][3] += a4.w * b4.w;
        }
        __syncthreads();
    }

    float4 bias = *(const float4*)(b1 + 4 * tx);
#pragma unroll
    for (int j = 0; j < 4; ++j) {
        int gm = m0 + 4 * ty + j;
        if (gm < M) {
            float4 o;
            o.x = acc[j][0] + bias.x;
            o.y = acc[j][1] + bias.y;
            o.z = acc[j][2] + bias.z;
            o.w = acc[j][3] + bias.w;
            *(float4*)(out + (size_t)gm * 64 + 4 * tx) = o;
        }
    }
}

// ---------------- launcher ---------------------------------------------------
extern "C" void kernel_launch(void* const* d_in, const int* in_sizes, int n_in,
                              void* d_out, int out_size) {
    const float* x  = (const float*)d_in[0];
    const int*   ei = (const int*)d_in[1];
    const float* ew = (const float*)d_in[2];
    const float* W0 = (const float*)d_in[3];
    const float* b0 = (const float*)d_in[4];
    const float* W1 = (const float*)d_in[5];
    const float* b1 = (const float*)d_in[6];
    float* out = (float*)d_out;

    int n = in_sizes[0] / DD;
    int e = in_sizes[2];
    const int* row = ei;
    const int* col = ei + e;

    int n2 = n * DD / 2;
    init_cvt_kernel<<<(n2 + 255) / 256, 256>>>(x, n, n2);     // launch 1
    hist_kernel<<<(e + 255) / 256, 256>>>(row, ew, e);        // launch 2
    dinv_kernel<<<(n + 255) / 256, 256>>>(n);                 // launch 3
    scan_kernel<<<1, 1024>>>(n);                              // launch 4
    scatter_kernel<<<(e + 255) / 256, 256>>>(row, col, ew, e);// launch 5

    int spmm_grid = (n + 7) / 8;   // 8 warps (rows) per 256-thread block
    for (int it = 0; it < KPROP; ++it)
        spmm_kernel<<<spmm_grid, 256>>>(it, n);               // launches 6..15

    int mblocks = (n + 63) / 64;
    gemm1_kernel<<<dim3(mblocks, 4), 256>>>(x, W0, b0, n);
    gemm2_kernel<<<dim3(mblocks, 1), 256>>>(W1, b1, out, n);
}

// round 8
// speedup vs baseline: 1.3750x; 1.2179x over previous
#include <cuda_runtime.h>
#include <cuda_fp16.h>
#include <cuda_bf16.h>

#define NN 100000
#define EE 1600000
#define DD 64
#define KPROP 10
#define SC 1024          // elements per scan block

// ---------------- scratch (static device globals; no runtime allocation) ----
__device__ float  g_deg[NN];
__device__ float  g_dinv[NN];
__device__ float  g_selfw[NN];
__device__ int    g_cnt[NN];
__device__ int    g_rowptr[NN + 1];
__device__ int    g_bsum[128];
__device__ int    g_boff[128];
__device__ int    g_cols[EE];
__device__ float  g_wn[EE];
__device__ __align__(16) __half g_x16[NN * DD];   // fp16 copy of x
__device__ __align__(16) __half g_h16A[NN * DD];  // ping
__device__ __align__(16) __half g_h16B[NN * DD];  // pong
__device__ __align__(16) float  g_acc[NN * DD];   // fp32 acc of sum_l A^l x
__device__ __align__(16) float  g_z[NN * 256];

// ---------------- fused: deg=1, cnt=0, x->fp16 -------------------------------
__global__ void init_cvt_kernel(const float* __restrict__ x, int n, int n2) {
    int i = blockIdx.x * blockDim.x + threadIdx.x;
    if (i < n) { g_deg[i] = 1.0f; g_cnt[i] = 0; }
    if (i < n2) {
        float2 f = ((const float2*)x)[i];
        ((__half2*)g_x16)[i] = __floats2half2_rn(f.x, f.y);
    }
}

// ---------------- degree + row histogram ------------------------------------
__global__ void hist_kernel(const int* __restrict__ row,
                            const float* __restrict__ w, int e) {
    int i = blockIdx.x * blockDim.x + threadIdx.x;
    if (i < e) {
        int r = row[i];
        atomicAdd(&g_deg[r], w[i]);
        atomicAdd(&g_cnt[r], 1);
    }
}

// ---------------- dinv + self-loop weight -----------------------------------
__global__ void dinv_kernel(int n) {
    int i = blockIdx.x * blockDim.x + threadIdx.x;
    if (i < n) {
        float di = rsqrtf(fmaxf(g_deg[i], 1e-12f));
        g_dinv[i] = di;
        g_selfw[i] = di * di;
    }
}

// ---------------- parallel scan: A (block sums) -----------------------------
__global__ void scanA_kernel(int n) {
    int b = blockIdx.x;
    int t = threadIdx.x;
    int base = b * SC + t * 4;
    int s = 0;
#pragma unroll
    for (int k = 0; k < 4; ++k) {
        int i = base + k;
        if (i < n) s += g_cnt[i];
    }
#pragma unroll
    for (int off = 16; off; off >>= 1)
        s += __shfl_down_sync(0xffffffffu, s, off);
    __shared__ int ws[8];
    if ((t & 31) == 0) ws[t >> 5] = s;
    __syncthreads();
    if (t < 8) {
        int v = ws[t];
#pragma unroll
        for (int off = 4; off; off >>= 1)
            v += __shfl_down_sync(0xffu, v, off);
        if (t == 0) g_bsum[b] = v;
    }
}

// ---------------- parallel scan: B (scan 98 block sums, one block) ----------
__global__ void scanB_kernel(int nb, int n) {
    __shared__ int sm[128];
    int t = threadIdx.x;
    int v = (t < nb) ? g_bsum[t] : 0;
    sm[t] = v;
    __syncthreads();
    for (int off = 1; off < 128; off <<= 1) {
        int u = (t >= off) ? sm[t - off] : 0;
        __syncthreads();
        sm[t] += u;
        __syncthreads();
    }
    if (t < nb) g_boff[t] = sm[t] - v;      // exclusive offset
    if (t == nb - 1) g_rowptr[n] = sm[t];   // total edge count
}

// ---------------- parallel scan: C (local scan + offset, reset cnt) ---------
__global__ void scanC_kernel(int n) {
    int b = blockIdx.x;
    int t = threadIdx.x;
    int lane = t & 31, wid = t >> 5;
    int base = b * SC + t * 4;

    int vals[4];
    int s = 0;
#pragma unroll
    for (int k = 0; k < 4; ++k) {
        int i = base + k;
        vals[k] = (i < n) ? g_cnt[i] : 0;
        s += vals[k];
    }
    // inclusive warp scan of per-thread sums
    int ss = s;
#pragma unroll
    for (int off = 1; off < 32; off <<= 1) {
        int u = __shfl_up_sync(0xffffffffu, ss, off);
        if (lane >= off) ss += u;
    }
    __shared__ int wtot[8];
    if (lane == 31) wtot[wid] = ss;
    __syncthreads();
    if (t == 0) {
        int run = 0;
#pragma unroll
        for (int wq = 0; wq < 8; ++wq) { int tmp = wtot[wq]; wtot[wq] = run; run += tmp; }
    }
    __syncthreads();
    int ex = ss - s + wtot[wid] + g_boff[b];  // exclusive prefix, first elem
#pragma unroll
    for (int k = 0; k < 4; ++k) {
        int i = base + k;
        if (i < n) {
            g_rowptr[i] = ex;
            ex += vals[k];
            g_cnt[i] = 0;   // reset: reused as scatter cursors
        }
    }
}

// ---------------- scatter edges into CSR with normalized weights ------------
__global__ void scatter_kernel(const int* __restrict__ row,
                               const int* __restrict__ col,
                               const float* __restrict__ w, int e) {
    int i = blockIdx.x * blockDim.x + threadIdx.x;
    if (i < e) {
        int r = row[i];
        int c = col[i];
        int pos = g_rowptr[r] + atomicAdd(&g_cnt[r], 1);
        g_cols[pos] = c;
        g_wn[pos] = g_dinv[r] * w[i] * g_dinv[c];
    }
}

// ---------------- SpMM step: warp per row, 8 lanes/edge, 4 edges/pass -------
__global__ void spmm_kernel(int iter, int n) {
    int gw = (blockIdx.x * blockDim.x + threadIdx.x) >> 5;
    if (gw >= n) return;
    int lane = threadIdx.x & 31;
    int g   = lane >> 3;   // edge group 0..3
    int sub = lane & 7;    // 16B chunk within 128B row

    const uint4* __restrict__ hin4 =
        (iter == 0) ? (const uint4*)g_x16
                    : ((iter & 1) ? (const uint4*)g_h16A
                                  : (const uint4*)g_h16B);
    uint4* __restrict__ hout4 =
        (iter & 1) ? (uint4*)g_h16B : (uint4*)g_h16A;

    float acc[8];
#pragma unroll
    for (int k = 0; k < 8; ++k) acc[k] = 0.0f;

    int s = g_rowptr[gw];
    int e = g_rowptr[gw + 1];
    int d = e - s;
    int full = d >> 2;
    int epb = s + g;

#pragma unroll 4
    for (int j = 0; j < full; ++j) {
        int ep = epb + j * 4;
        int   cc = __ldg(&g_cols[ep]);
        float ww = __ldg(&g_wn[ep]);
        uint4 v = hin4[(size_t)cc * 8 + sub];
        const __half2* hp = (const __half2*)&v;
#pragma unroll
        for (int q = 0; q < 4; ++q) {
            float2 f = __half22float2(hp[q]);
            acc[2 * q]     = fmaf(ww, f.x, acc[2 * q]);
            acc[2 * q + 1] = fmaf(ww, f.y, acc[2 * q + 1]);
        }
    }
    int r = d & 3;
    if (r) {
        int ep = epb + full * 4;
        int cc = 0;
        float ww = 0.0f;
        if (g < r) { cc = g_cols[ep]; ww = g_wn[ep]; }
        uint4 v = hin4[(size_t)cc * 8 + sub];
        const __half2* hp = (const __half2*)&v;
#pragma unroll
        for (int q = 0; q < 4; ++q) {
            float2 f = __half22float2(hp[q]);
            acc[2 * q]     = fmaf(ww, f.x, acc[2 * q]);
            acc[2 * q + 1] = fmaf(ww, f.y, acc[2 * q + 1]);
        }
    }

    // reduce the 4 edge groups (lanes differ in bits 3,4)
#pragma unroll
    for (int off = 8; off <= 16; off <<= 1)
#pragma unroll
        for (int k = 0; k < 8; ++k)
            acc[k] += __shfl_xor_sync(0xffffffffu, acc[k], off);

    if (lane < 8) {
        // self-loop contribution
        float sw = g_selfw[gw];
        uint4 own = hin4[(size_t)gw * 8 + sub];
        const __half2* op = (const __half2*)&own;
#pragma unroll
        for (int q = 0; q < 4; ++q) {
            float2 f = __half22float2(op[q]);
            acc[2 * q]     = fmaf(sw, f.x, acc[2 * q]);
            acc[2 * q + 1] = fmaf(sw, f.y, acc[2 * q + 1]);
        }
        // write fp16 row
        uint4 outv;
        __half2* ov = (__half2*)&outv;
#pragma unroll
        for (int q = 0; q < 4; ++q)
            ov[q] = __floats2half2_rn(acc[2 * q], acc[2 * q + 1]);
        hout4[(size_t)gw * 8 + sub] = outv;

        // fp32 acc RMW (row = 16 float4; this lane owns 2 of them)
        float4* accp = (float4*)g_acc;
        size_t ai = (size_t)gw * 16 + sub * 2;
        if (iter == 0) {
            accp[ai]     = make_float4(acc[0], acc[1], acc[2], acc[3]);
            accp[ai + 1] = make_float4(acc[4], acc[5], acc[6], acc[7]);
        } else {
            float4 t0 = accp[ai], t1 = accp[ai + 1];
            t0.x += acc[0]; t0.y += acc[1]; t0.z += acc[2]; t0.w += acc[3];
            t1.x += acc[4]; t1.y += acc[5]; t1.z += acc[6]; t1.w += acc[7];
            accp[ai] = t0; accp[ai + 1] = t1;
        }
    }
}

// ---------------- GEMM1: z = relu((0.1x + 0.09acc) @ W0 + b0)   [M,64]x[64,256]
__global__ void gemm1_kernel(const float* __restrict__ x,
                             const float* __restrict__ W0,
                             const float* __restrict__ b0, int M) {
    __shared__ float As[16][68];
    __shared__ float Bs[16][68];
    int m0 = blockIdx.x * 64;
    int n0 = blockIdx.y * 64;
    int tid = threadIdx.x;
    int ty = tid >> 4, tx = tid & 15;

    float acc[4][4];
#pragma unroll
    for (int i = 0; i < 4; ++i)
#pragma unroll
        for (int j = 0; j < 4; ++j) acc[i][j] = 0.0f;

    int am = tid >> 2;
    int ak = (tid & 3) * 4;
    int kb = tid >> 4;
    int bn = (tid & 15) * 4;

    for (int k0 = 0; k0 < 64; k0 += 16) {
        int gm = m0 + am;
        float4 av = make_float4(0.f, 0.f, 0.f, 0.f);
        if (gm < M) {
            float4 xv = *(const float4*)(x + (size_t)gm * 64 + k0 + ak);
            float4 cv = *(const float4*)(g_acc + (size_t)gm * 64 + k0 + ak);
            av.x = 0.1f * xv.x + 0.09f * cv.x;
            av.y = 0.1f * xv.y + 0.09f * cv.y;
            av.z = 0.1f * xv.z + 0.09f * cv.z;
            av.w = 0.1f * xv.w + 0.09f * cv.w;
        }
        As[ak + 0][am] = av.x;
        As[ak + 1][am] = av.y;
        As[ak + 2][am] = av.z;
        As[ak + 3][am] = av.w;
        *(float4*)&Bs[kb][bn] =
            *(const float4*)(W0 + (size_t)(k0 + kb) * 256 + n0 + bn);
        __syncthreads();
#pragma unroll
        for (int k = 0; k < 16; ++k) {
            float4 a4 = *(float4*)&As[k][4 * ty];
            float4 b4 = *(float4*)&Bs[k][4 * tx];
            acc[0][0] += a4.x * b4.x; acc[0][1] += a4.x * b4.y;
            acc[0][2] += a4.x * b4.z; acc[0][3] += a4.x * b4.w;
            acc[1][0] += a4.y * b4.x; acc[1][1] += a4.y * b4.y;
            acc[1][2] += a4.y * b4.z; acc[1][3] += a4.y * b4.w;
            acc[2][0] += a4.z * b4.x; acc[2][1] += a4.z * b4.y;
            acc[2][2] += a4.z * b4.z; acc[2][3] += a4.z * b4.w;
            acc[3][0] += a4.w * b4.x; acc[3][1] += a4.w * b4.y;
            acc[3][2] += a4.w * b4.z; acc[3][3] += a4.w * b4.w;
        }
        __syncthreads();
    }

    float4 bias = *(const float4*)(b0 + n0 + 4 * tx);
#pragma unroll
    for (int j = 0; j < 4; ++j) {
        int gm = m0 + 4 * ty + j;
        if (gm < M) {
            float4 o;
            o.x = fmaxf(acc[j][0] + bias.x, 0.0f);
            o.y = fmaxf(acc[j][1] + bias.y, 0.0f);
            o.z = fmaxf(acc[j][2] + bias.z, 0.0f);
            o.w = fmaxf(acc[j][3] + bias.w, 0.0f);
            *(float4*)(g_z + (size_t)gm * 256 + n0 + 4 * tx) = o;
        }
    }
}

// ---------------- GEMM2: out = z @ W1 + b1   [M,256]x[256,64] ----------------
__global__ void gemm2_kernel(const float* __restrict__ W1,
                             const float* __restrict__ b1,
                             float* __restrict__ out, int M) {
    __shared__ float As[16][68];
    __shared__ float Bs[16][68];
    int m0 = blockIdx.x * 64;
    int tid = threadIdx.x;
    int ty = tid >> 4, tx = tid & 15;

    float acc[4][4];
#pragma unroll
    for (int i = 0; i < 4; ++i)
#pragma unroll
        for (int j = 0; j < 4; ++j) acc[i][j] = 0.0f;

    int am = tid >> 2;
    int ak = (tid & 3) * 4;
    int kb = tid >> 4;
    int bn = (tid & 15) * 4;

    for (int k0 = 0; k0 < 256; k0 += 16) {
        int gm = m0 + am;
        float4 av = make_float4(0.f, 0.f, 0.f, 0.f);
        if (gm < M) av = *(const float4*)(g_z + (size_t)gm * 256 + k0 + ak);
        As[ak + 0][am] = av.x;
        As[ak + 1][am] = av.y;
        As[ak + 2][am] = av.z;
        As[ak + 3][am] = av.w;
        *(float4*)&Bs[kb][bn] =
            *(const float4*)(W1 + (size_t)(k0 + kb) * 64 + bn);
        __syncthreads();
#pragma unroll
        for (int k = 0; k < 16; ++k) {
            float4 a4 = *(float4*)&As[k][4 * ty];
            float4 b4 = *(float4*)&Bs[k][4 * tx];
            acc[0][0] += a4.x * b4.x; acc[0][1] += a4.x * b4.y;
            acc[0][2] += a4.x * b4.z; acc[0][3] += a4.x * b4.w;
            acc[1][0] += a4.y * b4.x; acc[1][1] += a4.y * b4.y;
            acc[1][2] += a4.y * b4.z; acc[1][3] += a4.y * b4.w;
            acc[2][0] += a4.z * b4.x; acc[2][1] += a4.z * b4.y;
            acc[2][2] += a4.z * b4.z; acc[2][3] += a4.z * b4.w;
            acc[3][0] += a4.w * b4.x; acc[3][1] += a4.w * b4.y;
            acc[3][2] += a4.w * b4.z; acc[3][3] += a4.w * b4.w;
        }
        __syncthreads();
    }

    float4 bias = *(const float4*)(b1 + 4 * tx);
#pragma unroll
    for (int j = 0; j < 4; ++j) {
        int gm = m0 + 4 * ty + j;
        if (gm < M) {
            float4 o;
            o.x = acc[j][0] + bias.x;
            o.y = acc[j][1] + bias.y;
            o.z = acc[j][2] + bias.z;
            o.w = acc[j][3] + bias.w;
            *(float4*)(out + (size_t)gm * 64 + 4 * tx) = o;
        }
    }
}

// ---------------- launcher ---------------------------------------------------
extern "C" void kernel_launch(void* const* d_in, const int* in_sizes, int n_in,
                              void* d_out, int out_size) {
    const float* x  = (const float*)d_in[0];
    const int*   ei = (const int*)d_in[1];
    const float* ew = (const float*)d_in[2];
    const float* W0 = (const float*)d_in[3];
    const float* b0 = (const float*)d_in[4];
    const float* W1 = (const float*)d_in[5];
    const float* b1 = (const float*)d_in[6];
    float* out = (float*)d_out;

    int n = in_sizes[0] / DD;
    int e = in_sizes[2];
    const int* row = ei;
    const int* col = ei + e;

    int n2 = n * DD / 2;
    int nb = (n + SC - 1) / SC;   // scan blocks (98 for n=100000)

    init_cvt_kernel<<<(n2 + 255) / 256, 256>>>(x, n, n2);
    hist_kernel<<<(e + 255) / 256, 256>>>(row, ew, e);
    dinv_kernel<<<(n + 255) / 256, 256>>>(n);
    scanA_kernel<<<nb, 256>>>(n);
    scanB_kernel<<<1, 128>>>(nb, n);
    scanC_kernel<<<nb, 256>>>(n);
    scatter_kernel<<<(e + 255) / 256, 256>>>(row, col, ew, e);

    int spmm_grid = (n + 7) / 8;   // 8 warps (rows) per 256-thread block
    for (int it = 0; it < KPROP; ++it)
        spmm_kernel<<<spmm_grid, 256>>>(it, n);

    int mblocks = (n + 63) / 64;
    gemm1_kernel<<<dim3(mblocks, 4), 256>>>(x, W0, b0, n);
    gemm2_kernel<<<dim3(mblocks, 1), 256>>>(W1, b1, out, n);
}